// round 16
// baseline (speedup 1.0000x reference)
#include <cuda_runtime.h>
#include <cuda_fp16.h>

#define BT    8192          // B*T
#define DIM   256
#define NH    3
#define NNEG  128
#define PREDN (NH*DIM)      // 768

__device__ float         g_allz [BT * DIM];    // normalized z table, fp32 (8 MB) — pos logits
__device__ unsigned      g_allzq[BT * DIM / 4];// normalized z table, int8x4 (2 MB) — neg gathers
__device__ __half        g_a16  [BT * DIM];    // raw z, fp16 (4 MB) — GEMM A operand
__device__ __half        g_w16  [PREDN * DIM]; // preds, fp16 (0.4 MB) — GEMM B operand
__device__ float         g_pred [BT * PREDN];  // z_pred for all horizons (24 MB)
__device__ float         g_row  [NH * BT];     // per-row weighted losses
__device__ int           g_is64;

__constant__ int   c_k[3] = {1, 5, 21};
__constant__ float c_w[3] = {0.6004450f, 0.26852716f, 0.13102784f}; // (1/sqrt k)/tot

// logit = dot_int * (1/(127*127)) * (1/0.07)
#define LSCALE 8.857410e-4f

// ---- helpers -------------------------------------------------------------
__device__ __forceinline__ float warp_sum(float v) {
    #pragma unroll
    for (int o = 16; o; o >>= 1) v += __shfl_xor_sync(0xffffffffu, v, o);
    return v;
}
__device__ __forceinline__ int dp4a_s(unsigned a, unsigned b, int c) {
    return __dp4a((int)a, (int)b, c);
}
// one-instruction masked warp-segment integer reduction (sm_80+)
__device__ __forceinline__ int redux_add_s32(int v, unsigned mask) {
    int r;
    asm volatile("redux.sync.add.s32 %0, %1, %2;" : "=r"(r) : "r"(v), "r"(mask));
    return r;
}
__device__ __forceinline__ unsigned pack_s8x4(float a, float b, float c, float d) {
    int qa = __float2int_rn(a * 127.0f);
    int qb = __float2int_rn(b * 127.0f);
    int qc = __float2int_rn(c * 127.0f);
    int qd = __float2int_rn(d * 127.0f);
    return (qa & 0xff) | ((qb & 0xff) << 8) | ((qc & 0xff) << 16) | ((qd & 0xff) << 24);
}
__device__ __forceinline__ unsigned sptr(const void* p) {
    return (unsigned)__cvta_generic_to_shared(p);
}
__device__ __forceinline__ void cp16(unsigned dst, const void* src) {
    asm volatile("cp.async.cg.shared.global [%0], [%1], 16;" :: "r"(dst), "l"(src));
}

// ---------------------------------------------------------------------------
__global__ void detect_kernel(const long long* __restrict__ neg) {
    int lane = threadIdx.x;
    unsigned long long v0 = (unsigned long long)neg[lane];
    unsigned long long v1 = (unsigned long long)neg[lane + 32];
    int bad = (v0 >= (unsigned long long)BT) || (v1 >= (unsigned long long)BT);
    unsigned mask = __ballot_sync(0xffffffffu, bad);
    if (lane == 0) g_is64 = (mask == 0u);
}

// ---------------------------------------------------------------------------
// Normalize rows -> g_allz (fp32), g_allzq (int8); raw fp16 copy -> g_a16.
// ---------------------------------------------------------------------------
__global__ __launch_bounds__(256) void norm_kernel(const float* __restrict__ z) {
    int warp = threadIdx.x >> 5;
    int lane = threadIdx.x & 31;
    int row  = blockIdx.x * 8 + warp;

    const float4* src = (const float4*)(z + (long long)row * DIM);
    float4 a = src[lane];
    float4 b = src[lane + 32];

    {
        __half2* a16 = (__half2*)(g_a16 + (long long)row * DIM);
        a16[2*lane+0]    = __floats2half2_rn(a.x, a.y);
        a16[2*lane+1]    = __floats2half2_rn(a.z, a.w);
        a16[64+2*lane+0] = __floats2half2_rn(b.x, b.y);
        a16[64+2*lane+1] = __floats2half2_rn(b.z, b.w);
    }

    float s = a.x*a.x + a.y*a.y + a.z*a.z + a.w*a.w
            + b.x*b.x + b.y*b.y + b.z*b.z + b.w*b.w;
    s = warp_sum(s);
    float inv = 1.0f / fmaxf(sqrtf(s), 1e-12f);

    a.x *= inv; a.y *= inv; a.z *= inv; a.w *= inv;
    b.x *= inv; b.y *= inv; b.z *= inv; b.w *= inv;

    float4* dst = (float4*)(g_allz + (long long)row * DIM);
    dst[lane]      = a;
    dst[lane + 32] = b;

    unsigned* rq = g_allzq + (long long)row * (DIM / 4);
    rq[lane]      = pack_s8x4(a.x, a.y, a.z, a.w);
    rq[32 + lane] = pack_s8x4(b.x, b.y, b.z, b.w);
}

// ---------------------------------------------------------------------------
// preds f32 -> f16 (196608 elems, 4 per thread).
// ---------------------------------------------------------------------------
__global__ __launch_bounds__(256) void predconv_kernel(const float* __restrict__ w) {
    int i = blockIdx.x * 256 + threadIdx.x;
    float4 v = *((const float4*)w + i);
    __half2* out = (__half2*)g_w16 + 2 * i;
    out[0] = __floats2half2_rn(v.x, v.y);
    out[1] = __floats2half2_rn(v.z, v.w);
}

// ---------------------------------------------------------------------------
// HMMA GEMM, 3-stage cp.async pipeline, ONE __syncthreads per K-step.
// BM=128, BN=64, BK=32; 8 warps (4x2); warp tile 32x32 = 2x4 m16n8k16.
// Smem: 3 stages x 15360 B = 46 KB (under 48 KB static limit).
// ---------------------------------------------------------------------------
#define NKT (DIM / 32)      // 8 K-steps

__global__ __launch_bounds__(256) void gemm16_kernel(const __half* __restrict__ A16,
                                                     const __half* __restrict__ W16) {
    __shared__ __half As[3][128 * 40];
    __shared__ __half Bs[3][64 * 40];

    const int tid  = threadIdx.x;
    const int lane = tid & 31, warp = tid >> 5;
    const int bn = blockIdx.x, bm = blockIdx.y;
    const int wm = warp >> 1, wn = warp & 1;

    float c[2][4][4];
    #pragma unroll
    for (int i = 0; i < 2; ++i)
        #pragma unroll
        for (int j = 0; j < 4; ++j)
            #pragma unroll
            for (int q = 0; q < 4; ++q) c[i][j][q] = 0.0f;

    const __half* Ab = A16 + (size_t)(bm * 128) * DIM;
    const __half* Wb = W16 + (size_t)(bn * 64)  * DIM;

    const int a_r0 = tid >> 2, a_q = tid & 3;
    const int b_r  = tid >> 2, b_q = tid & 3;

    const int a_row = wm * 32 + (lane & 15);
    const int a_col = (lane >> 4) * 8;
    const int b_row = wn * 32 + (lane & 7) + ((lane >> 4) << 3);
    const int b_col = ((lane >> 3) & 1) * 8;

    auto issue = [&](int kt, int st) {
        int k0 = kt * 32;
        cp16(sptr(&As[st][a_r0 * 40 + a_q * 8]),        Ab + a_r0 * DIM + k0 + a_q * 8);
        cp16(sptr(&As[st][(a_r0 + 64) * 40 + a_q * 8]), Ab + (a_r0 + 64) * DIM + k0 + a_q * 8);
        cp16(sptr(&Bs[st][b_r * 40 + b_q * 8]),         Wb + b_r * DIM + k0 + b_q * 8);
    };

    issue(0, 0);
    asm volatile("cp.async.commit_group;");
    issue(1, 1);
    asm volatile("cp.async.commit_group;");

    int cur = 0;
    for (int kt = 0; kt < NKT; ++kt) {
        asm volatile("cp.async.wait_group 1;");
        __syncthreads();

        // refill stage (kt+2): its previous readers finished at iter kt-1,
        // guaranteed by the sync above.
        int nst = cur + 2; if (nst >= 3) nst -= 3;
        if (kt + 2 < NKT) issue(kt + 2, nst);
        asm volatile("cp.async.commit_group;");

        #pragma unroll
        for (int ks = 0; ks < 32; ks += 16) {
            unsigned a[2][4], bfr[2][4];
            #pragma unroll
            for (int tm = 0; tm < 2; ++tm) {
                unsigned addr = sptr(&As[cur][(a_row + tm * 16) * 40 + a_col + ks]);
                asm volatile("ldmatrix.sync.aligned.m8n8.x4.shared.b16 {%0,%1,%2,%3},[%4];"
                    : "=r"(a[tm][0]), "=r"(a[tm][1]), "=r"(a[tm][2]), "=r"(a[tm][3])
                    : "r"(addr));
            }
            #pragma unroll
            for (int g = 0; g < 2; ++g) {
                unsigned addr = sptr(&Bs[cur][(b_row + g * 16) * 40 + b_col + ks]);
                asm volatile("ldmatrix.sync.aligned.m8n8.x4.shared.b16 {%0,%1,%2,%3},[%4];"
                    : "=r"(bfr[g][0]), "=r"(bfr[g][1]), "=r"(bfr[g][2]), "=r"(bfr[g][3])
                    : "r"(addr));
            }
            #pragma unroll
            for (int tm = 0; tm < 2; ++tm)
                #pragma unroll
                for (int tn = 0; tn < 4; ++tn) {
                    unsigned b0 = bfr[tn >> 1][(tn & 1) * 2 + 0];
                    unsigned b1 = bfr[tn >> 1][(tn & 1) * 2 + 1];
                    asm volatile(
                        "mma.sync.aligned.m16n8k16.row.col.f32.f16.f16.f32 "
                        "{%0,%1,%2,%3},{%4,%5,%6,%7},{%8,%9},{%0,%1,%2,%3};"
                        : "+f"(c[tm][tn][0]), "+f"(c[tm][tn][1]),
                          "+f"(c[tm][tn][2]), "+f"(c[tm][tn][3])
                        : "r"(a[tm][0]), "r"(a[tm][1]), "r"(a[tm][2]), "r"(a[tm][3]),
                          "r"(b0), "r"(b1));
                }
        }
        cur = (cur + 1 == 3) ? 0 : cur + 1;
    }

    const int cm = lane >> 2, cn2 = (lane & 3) * 2;
    #pragma unroll
    for (int tm = 0; tm < 2; ++tm)
        #pragma unroll
        for (int tn = 0; tn < 4; ++tn) {
            int row0 = bm * 128 + wm * 32 + tm * 16 + cm;
            int col  = bn * 64 + wn * 32 + tn * 8 + cn2;
            float* p0 = g_pred + (size_t)row0 * PREDN + col;
            *(float2*)p0 = make_float2(c[tm][tn][0], c[tm][tn][1]);
            *(float2*)(p0 + 8 * PREDN) = make_float2(c[tm][tn][2], c[tm][tn][3]);
        }
}

// ---------------------------------------------------------------------------
// Loss: one warp per row, barrier-free, int8 DP4A; per-segment dot reduced
// with a single redux.sync.add.s32 (replaces 3 SHFL + 3 FADD, ~78cyc chain).
// ---------------------------------------------------------------------------
__global__ __launch_bounds__(256, 5) void loss_kernel(const void* __restrict__ negv) {
    const int warp = threadIdx.x >> 5;
    const int lane = threadIdx.x & 31;
    const int gid  = blockIdx.x * 8 + warp;
    const int hi   = gid >> 13;
    const int n    = gid & (BT - 1);

    const int k = c_k[hi];
    const int L = 512 - k;
    const int NR = 16 * L;

    if (n >= NR) {
        if (lane == 0) g_row[gid] = 0.0f;
        return;
    }

    const int b = n / L;
    const int l = n - b * L;
    const int m = b * 512 + l;

    __shared__ unsigned syq_all[8 * 64];
    unsigned* syq = syq_all + warp * 64;

    const float4* yp = (const float4*)(g_pred + (long long)m * PREDN + hi * DIM);
    const float4* zp = (const float4*)(g_allz + (long long)(m + k) * DIM);
    float4 ya = yp[lane], yb = yp[lane + 32];
    float4 za = zp[lane], zb = zp[lane + 32];
    float v1 = ya.x*ya.x + ya.y*ya.y + ya.z*ya.z + ya.w*ya.w
             + yb.x*yb.x + yb.y*yb.y + yb.z*yb.z + yb.w*yb.w;
    float v2 = ya.x*za.x + ya.y*za.y + ya.z*za.z + ya.w*za.w
             + yb.x*zb.x + yb.y*zb.y + yb.z*zb.z + yb.w*zb.w;
    v1 = warp_sum(v1);
    v2 = warp_sum(v2);
    const float invn = 1.0f / fmaxf(sqrtf(v1), 1e-12f);
    const float pos  = v2 * invn * 14.285714286f;

    syq[lane]      = pack_s8x4(ya.x*invn, ya.y*invn, ya.z*invn, ya.w*invn);
    syq[32 + lane] = pack_s8x4(yb.x*invn, yb.y*invn, yb.z*invn, yb.w*invn);
    __syncwarp();

    const int seg = lane >> 3;
    const int c   = lane & 7;
    const unsigned segmask = 0xFFu << (seg * 8);
    uint4 tq0 = *(const uint4*)(syq + 4*c);
    uint4 tq1 = *(const uint4*)(syq + 32 + 4*c);

    const int is64 = g_is64;
    const long long base = ((long long)(hi * BT + n)) * NNEG;
    const int* neg32 = (const int*)negv;

    float ssum = 0.0f;
    #pragma unroll 8
    for (int pass = 0; pass < 32; ++pass) {
        int j = (pass << 2) + seg;
        long long o = base + j;
        int idx = neg32[is64 ? (o << 1) : o];
        const uint4* rowp = (const uint4*)(g_allzq + ((size_t)idx << 6));
        uint4 u0 = rowp[c];
        uint4 u1 = rowp[c + 8];

        int acc = dp4a_s(u0.x, tq0.x, 0);
        acc = dp4a_s(u0.y, tq0.y, acc);
        acc = dp4a_s(u0.z, tq0.z, acc);
        acc = dp4a_s(u0.w, tq0.w, acc);
        acc = dp4a_s(u1.x, tq1.x, acc);
        acc = dp4a_s(u1.y, tq1.y, acc);
        acc = dp4a_s(u1.z, tq1.z, acc);
        acc = dp4a_s(u1.w, tq1.w, acc);

        int d = redux_add_s32(acc, segmask);
        ssum += __expf((float)d * LSCALE);
    }

    ssum += __shfl_xor_sync(0xffffffffu, ssum, 8);
    ssum += __shfl_xor_sync(0xffffffffu, ssum, 16);

    if (lane == 0) {
        float lse = logf(ssum + expf(pos));
        g_row[gid] = c_w[hi] * (lse - pos) / (float)NR;
    }
}

// ---------------------------------------------------------------------------
__global__ __launch_bounds__(256) void reduce_kernel(float* __restrict__ out) {
    __shared__ float s[256];
    float acc = 0.0f;
    for (int i = threadIdx.x; i < NH * BT; i += 256) acc += g_row[i];
    s[threadIdx.x] = acc;
    __syncthreads();
    for (int st = 128; st; st >>= 1) {
        if (threadIdx.x < st) s[threadIdx.x] += s[threadIdx.x + st];
        __syncthreads();
    }
    if (threadIdx.x == 0) out[0] = s[0];
}

// ---------------------------------------------------------------------------
extern "C" void kernel_launch(void* const* d_in, const int* in_sizes, int n_in,
                              void* d_out, int out_size) {
    const float* z_seq = (const float*)d_in[0];   // (16,512,256) f32
    const float* preds = (const float*)d_in[1];   // (3,256,256)  f32
    const void*  neg   = d_in[2];                 // (3,8192,128) int32 or int64

    __half* a16 = nullptr;  __half* w16 = nullptr;
    cudaGetSymbolAddress((void**)&a16, g_a16);
    cudaGetSymbolAddress((void**)&w16, g_w16);

    detect_kernel<<<1, 32>>>((const long long*)neg);
    norm_kernel<<<BT / 8, 256>>>(z_seq);
    predconv_kernel<<<PREDN * DIM / 4 / 256, 256>>>(preds);
    gemm16_kernel<<<dim3(PREDN / 64, BT / 128), 256>>>(a16, w16);
    loss_kernel<<<NH * BT / 8, 256>>>(neg);
    reduce_kernel<<<1, 256>>>((float*)d_out);
}

// round 17
// speedup vs baseline: 1.0025x; 1.0025x over previous
#include <cuda_runtime.h>
#include <cuda_fp16.h>

#define BT    8192          // B*T
#define DIM   256
#define NH    3
#define NNEG  128
#define PREDN (NH*DIM)      // 768

__device__ float         g_allz [BT * DIM];    // normalized z table, fp32 (8 MB) — pos logits
__device__ unsigned      g_allzq[BT * DIM / 4];// normalized z table, int8x4 (2 MB) — neg gathers
__device__ __half        g_a16  [BT * DIM];    // raw z, fp16 (4 MB) — GEMM A operand
__device__ __half        g_w16  [PREDN * DIM]; // preds, fp16 (0.4 MB) — GEMM B operand
__device__ float         g_pred [BT * PREDN];  // z_pred for all horizons (24 MB)
__device__ float         g_row  [NH * BT];     // per-row weighted losses
__device__ int           g_is64;

__constant__ int   c_k[3] = {1, 5, 21};
__constant__ float c_w[3] = {0.6004450f, 0.26852716f, 0.13102784f}; // (1/sqrt k)/tot

// logit = dot_int * (1/(127*127)) * (1/0.07)
#define LSCALE 8.857410e-4f

// ---- helpers -------------------------------------------------------------
__device__ __forceinline__ float warp_sum(float v) {
    #pragma unroll
    for (int o = 16; o; o >>= 1) v += __shfl_xor_sync(0xffffffffu, v, o);
    return v;
}
__device__ __forceinline__ int dp4a_s(unsigned a, unsigned b, int c) {
    return __dp4a((int)a, (int)b, c);
}
// one-instruction masked warp-segment integer reduction (sm_80+)
__device__ __forceinline__ int redux_add_s32(int v, unsigned mask) {
    int r;
    asm volatile("redux.sync.add.s32 %0, %1, %2;" : "=r"(r) : "r"(v), "r"(mask));
    return r;
}
__device__ __forceinline__ unsigned pack_s8x4(float a, float b, float c, float d) {
    int qa = __float2int_rn(a * 127.0f);
    int qb = __float2int_rn(b * 127.0f);
    int qc = __float2int_rn(c * 127.0f);
    int qd = __float2int_rn(d * 127.0f);
    return (qa & 0xff) | ((qb & 0xff) << 8) | ((qc & 0xff) << 16) | ((qd & 0xff) << 24);
}
__device__ __forceinline__ unsigned sptr(const void* p) {
    return (unsigned)__cvta_generic_to_shared(p);
}
__device__ __forceinline__ void cp16(unsigned dst, const void* src) {
    asm volatile("cp.async.cg.shared.global [%0], [%1], 16;" :: "r"(dst), "l"(src));
}

// ---------------------------------------------------------------------------
__global__ void detect_kernel(const long long* __restrict__ neg) {
    int lane = threadIdx.x;
    unsigned long long v0 = (unsigned long long)neg[lane];
    unsigned long long v1 = (unsigned long long)neg[lane + 32];
    int bad = (v0 >= (unsigned long long)BT) || (v1 >= (unsigned long long)BT);
    unsigned mask = __ballot_sync(0xffffffffu, bad);
    if (lane == 0) g_is64 = (mask == 0u);
}

// ---------------------------------------------------------------------------
// Normalize rows -> g_allz (fp32), g_allzq (int8); raw fp16 copy -> g_a16.
// ---------------------------------------------------------------------------
__global__ __launch_bounds__(256) void norm_kernel(const float* __restrict__ z) {
    int warp = threadIdx.x >> 5;
    int lane = threadIdx.x & 31;
    int row  = blockIdx.x * 8 + warp;

    const float4* src = (const float4*)(z + (long long)row * DIM);
    float4 a = src[lane];
    float4 b = src[lane + 32];

    {
        __half2* a16 = (__half2*)(g_a16 + (long long)row * DIM);
        a16[2*lane+0]    = __floats2half2_rn(a.x, a.y);
        a16[2*lane+1]    = __floats2half2_rn(a.z, a.w);
        a16[64+2*lane+0] = __floats2half2_rn(b.x, b.y);
        a16[64+2*lane+1] = __floats2half2_rn(b.z, b.w);
    }

    float s = a.x*a.x + a.y*a.y + a.z*a.z + a.w*a.w
            + b.x*b.x + b.y*b.y + b.z*b.z + b.w*b.w;
    s = warp_sum(s);
    float inv = 1.0f / fmaxf(sqrtf(s), 1e-12f);

    a.x *= inv; a.y *= inv; a.z *= inv; a.w *= inv;
    b.x *= inv; b.y *= inv; b.z *= inv; b.w *= inv;

    float4* dst = (float4*)(g_allz + (long long)row * DIM);
    dst[lane]      = a;
    dst[lane + 32] = b;

    unsigned* rq = g_allzq + (long long)row * (DIM / 4);
    rq[lane]      = pack_s8x4(a.x, a.y, a.z, a.w);
    rq[32 + lane] = pack_s8x4(b.x, b.y, b.z, b.w);
}

// ---------------------------------------------------------------------------
// preds f32 -> f16 (196608 elems, 4 per thread).
// ---------------------------------------------------------------------------
__global__ __launch_bounds__(256) void predconv_kernel(const float* __restrict__ w) {
    int i = blockIdx.x * 256 + threadIdx.x;
    float4 v = *((const float4*)w + i);
    __half2* out = (__half2*)g_w16 + 2 * i;
    out[0] = __floats2half2_rn(v.x, v.y);
    out[1] = __floats2half2_rn(v.z, v.w);
}

// ---------------------------------------------------------------------------
// HMMA GEMM, 3-stage cp.async pipeline, ONE __syncthreads per K-step.
// BM=128, BN=64, BK=32; 8 warps (4x2); warp tile 32x32 = 2x4 m16n8k16.
// Smem: 3 stages x 15360 B = 46 KB (under 48 KB static limit).
// ---------------------------------------------------------------------------
#define NKT (DIM / 32)      // 8 K-steps

__global__ __launch_bounds__(256) void gemm16_kernel(const __half* __restrict__ A16,
                                                     const __half* __restrict__ W16) {
    __shared__ __half As[3][128 * 40];
    __shared__ __half Bs[3][64 * 40];

    const int tid  = threadIdx.x;
    const int lane = tid & 31, warp = tid >> 5;
    const int bn = blockIdx.x, bm = blockIdx.y;
    const int wm = warp >> 1, wn = warp & 1;

    float c[2][4][4];
    #pragma unroll
    for (int i = 0; i < 2; ++i)
        #pragma unroll
        for (int j = 0; j < 4; ++j)
            #pragma unroll
            for (int q = 0; q < 4; ++q) c[i][j][q] = 0.0f;

    const __half* Ab = A16 + (size_t)(bm * 128) * DIM;
    const __half* Wb = W16 + (size_t)(bn * 64)  * DIM;

    const int a_r0 = tid >> 2, a_q = tid & 3;
    const int b_r  = tid >> 2, b_q = tid & 3;

    const int a_row = wm * 32 + (lane & 15);
    const int a_col = (lane >> 4) * 8;
    const int b_row = wn * 32 + (lane & 7) + ((lane >> 4) << 3);
    const int b_col = ((lane >> 3) & 1) * 8;

    auto issue = [&](int kt, int st) {
        int k0 = kt * 32;
        cp16(sptr(&As[st][a_r0 * 40 + a_q * 8]),        Ab + a_r0 * DIM + k0 + a_q * 8);
        cp16(sptr(&As[st][(a_r0 + 64) * 40 + a_q * 8]), Ab + (a_r0 + 64) * DIM + k0 + a_q * 8);
        cp16(sptr(&Bs[st][b_r * 40 + b_q * 8]),         Wb + b_r * DIM + k0 + b_q * 8);
    };

    issue(0, 0);
    asm volatile("cp.async.commit_group;");
    issue(1, 1);
    asm volatile("cp.async.commit_group;");

    int cur = 0;
    for (int kt = 0; kt < NKT; ++kt) {
        asm volatile("cp.async.wait_group 1;");
        __syncthreads();

        // refill stage (kt+2): its previous readers finished at iter kt-1,
        // guaranteed by the sync above.
        int nst = cur + 2; if (nst >= 3) nst -= 3;
        if (kt + 2 < NKT) issue(kt + 2, nst);
        asm volatile("cp.async.commit_group;");

        #pragma unroll
        for (int ks = 0; ks < 32; ks += 16) {
            unsigned a[2][4], bfr[2][4];
            #pragma unroll
            for (int tm = 0; tm < 2; ++tm) {
                unsigned addr = sptr(&As[cur][(a_row + tm * 16) * 40 + a_col + ks]);
                asm volatile("ldmatrix.sync.aligned.m8n8.x4.shared.b16 {%0,%1,%2,%3},[%4];"
                    : "=r"(a[tm][0]), "=r"(a[tm][1]), "=r"(a[tm][2]), "=r"(a[tm][3])
                    : "r"(addr));
            }
            #pragma unroll
            for (int g = 0; g < 2; ++g) {
                unsigned addr = sptr(&Bs[cur][(b_row + g * 16) * 40 + b_col + ks]);
                asm volatile("ldmatrix.sync.aligned.m8n8.x4.shared.b16 {%0,%1,%2,%3},[%4];"
                    : "=r"(bfr[g][0]), "=r"(bfr[g][1]), "=r"(bfr[g][2]), "=r"(bfr[g][3])
                    : "r"(addr));
            }
            #pragma unroll
            for (int tm = 0; tm < 2; ++tm)
                #pragma unroll
                for (int tn = 0; tn < 4; ++tn) {
                    unsigned b0 = bfr[tn >> 1][(tn & 1) * 2 + 0];
                    unsigned b1 = bfr[tn >> 1][(tn & 1) * 2 + 1];
                    asm volatile(
                        "mma.sync.aligned.m16n8k16.row.col.f32.f16.f16.f32 "
                        "{%0,%1,%2,%3},{%4,%5,%6,%7},{%8,%9},{%0,%1,%2,%3};"
                        : "+f"(c[tm][tn][0]), "+f"(c[tm][tn][1]),
                          "+f"(c[tm][tn][2]), "+f"(c[tm][tn][3])
                        : "r"(a[tm][0]), "r"(a[tm][1]), "r"(a[tm][2]), "r"(a[tm][3]),
                          "r"(b0), "r"(b1));
                }
        }
        cur = (cur + 1 == 3) ? 0 : cur + 1;
    }

    const int cm = lane >> 2, cn2 = (lane & 3) * 2;
    #pragma unroll
    for (int tm = 0; tm < 2; ++tm)
        #pragma unroll
        for (int tn = 0; tn < 4; ++tn) {
            int row0 = bm * 128 + wm * 32 + tm * 16 + cm;
            int col  = bn * 64 + wn * 32 + tn * 8 + cn2;
            float* p0 = g_pred + (size_t)row0 * PREDN + col;
            *(float2*)p0 = make_float2(c[tm][tn][0], c[tm][tn][1]);
            *(float2*)(p0 + 8 * PREDN) = make_float2(c[tm][tn][2], c[tm][tn][3]);
        }
}

// ---------------------------------------------------------------------------
// Loss: one warp per row, barrier-free, int8 DP4A; per-segment dot reduced
// with a single redux.sync.add.s32 (replaces 3 SHFL + 3 FADD, ~78cyc chain).
// ---------------------------------------------------------------------------
__global__ __launch_bounds__(256, 5) void loss_kernel(const void* __restrict__ negv) {
    const int warp = threadIdx.x >> 5;
    const int lane = threadIdx.x & 31;
    const int gid  = blockIdx.x * 8 + warp;
    const int hi   = gid >> 13;
    const int n    = gid & (BT - 1);

    const int k = c_k[hi];
    const int L = 512 - k;
    const int NR = 16 * L;

    if (n >= NR) {
        if (lane == 0) g_row[gid] = 0.0f;
        return;
    }

    const int b = n / L;
    const int l = n - b * L;
    const int m = b * 512 + l;

    __shared__ unsigned syq_all[8 * 64];
    unsigned* syq = syq_all + warp * 64;

    const float4* yp = (const float4*)(g_pred + (long long)m * PREDN + hi * DIM);
    const float4* zp = (const float4*)(g_allz + (long long)(m + k) * DIM);
    float4 ya = yp[lane], yb = yp[lane + 32];
    float4 za = zp[lane], zb = zp[lane + 32];
    float v1 = ya.x*ya.x + ya.y*ya.y + ya.z*ya.z + ya.w*ya.w
             + yb.x*yb.x + yb.y*yb.y + yb.z*yb.z + yb.w*yb.w;
    float v2 = ya.x*za.x + ya.y*za.y + ya.z*za.z + ya.w*za.w
             + yb.x*zb.x + yb.y*zb.y + yb.z*zb.z + yb.w*zb.w;
    v1 = warp_sum(v1);
    v2 = warp_sum(v2);
    const float invn = 1.0f / fmaxf(sqrtf(v1), 1e-12f);
    const float pos  = v2 * invn * 14.285714286f;

    syq[lane]      = pack_s8x4(ya.x*invn, ya.y*invn, ya.z*invn, ya.w*invn);
    syq[32 + lane] = pack_s8x4(yb.x*invn, yb.y*invn, yb.z*invn, yb.w*invn);
    __syncwarp();

    const int seg = lane >> 3;
    const int c   = lane & 7;
    const unsigned segmask = 0xFFu << (seg * 8);
    uint4 tq0 = *(const uint4*)(syq + 4*c);
    uint4 tq1 = *(const uint4*)(syq + 32 + 4*c);

    const int is64 = g_is64;
    const long long base = ((long long)(hi * BT + n)) * NNEG;
    const int* neg32 = (const int*)negv;

    float ssum = 0.0f;
    #pragma unroll 8
    for (int pass = 0; pass < 32; ++pass) {
        int j = (pass << 2) + seg;
        long long o = base + j;
        int idx = neg32[is64 ? (o << 1) : o];
        const uint4* rowp = (const uint4*)(g_allzq + ((size_t)idx << 6));
        uint4 u0 = rowp[c];
        uint4 u1 = rowp[c + 8];

        int acc = dp4a_s(u0.x, tq0.x, 0);
        acc = dp4a_s(u0.y, tq0.y, acc);
        acc = dp4a_s(u0.z, tq0.z, acc);
        acc = dp4a_s(u0.w, tq0.w, acc);
        acc = dp4a_s(u1.x, tq1.x, acc);
        acc = dp4a_s(u1.y, tq1.y, acc);
        acc = dp4a_s(u1.z, tq1.z, acc);
        acc = dp4a_s(u1.w, tq1.w, acc);

        int d = redux_add_s32(acc, segmask);
        ssum += __expf((float)d * LSCALE);
    }

    ssum += __shfl_xor_sync(0xffffffffu, ssum, 8);
    ssum += __shfl_xor_sync(0xffffffffu, ssum, 16);

    if (lane == 0) {
        float lse = logf(ssum + expf(pos));
        g_row[gid] = c_w[hi] * (lse - pos) / (float)NR;
    }
}

// ---------------------------------------------------------------------------
__global__ __launch_bounds__(256) void reduce_kernel(float* __restrict__ out) {
    __shared__ float s[256];
    float acc = 0.0f;
    for (int i = threadIdx.x; i < NH * BT; i += 256) acc += g_row[i];
    s[threadIdx.x] = acc;
    __syncthreads();
    for (int st = 128; st; st >>= 1) {
        if (threadIdx.x < st) s[threadIdx.x] += s[threadIdx.x + st];
        __syncthreads();
    }
    if (threadIdx.x == 0) out[0] = s[0];
}

// ---------------------------------------------------------------------------
extern "C" void kernel_launch(void* const* d_in, const int* in_sizes, int n_in,
                              void* d_out, int out_size) {
    const float* z_seq = (const float*)d_in[0];   // (16,512,256) f32
    const float* preds = (const float*)d_in[1];   // (3,256,256)  f32
    const void*  neg   = d_in[2];                 // (3,8192,128) int32 or int64

    __half* a16 = nullptr;  __half* w16 = nullptr;
    cudaGetSymbolAddress((void**)&a16, g_a16);
    cudaGetSymbolAddress((void**)&w16, g_w16);

    detect_kernel<<<1, 32>>>((const long long*)neg);
    norm_kernel<<<BT / 8, 256>>>(z_seq);
    predconv_kernel<<<PREDN * DIM / 4 / 256, 256>>>(preds);
    gemm16_kernel<<<dim3(PREDN / 64, BT / 128), 256>>>(a16, w16);
    loss_kernel<<<NH * BT / 8, 256>>>(neg);
    reduce_kernel<<<1, 256>>>((float*)d_out);
}